// round 1
// baseline (speedup 1.0000x reference)
#include <cuda_runtime.h>
#include <cuda_bf16.h>
#include <math.h>

// Problem constants
#define B_SZ 2
#define SEQ 2048
#define DMODEL 2048
#define NHEAD 16
#define DHEAD 128
#define MTOT (B_SZ * SEQ)   // 4096

// ---------------- scratch (device globals; no allocation allowed) ----------------
__device__ float g_q[(size_t)MTOT * DMODEL];
__device__ float g_k[(size_t)MTOT * DMODEL];
__device__ float g_v[(size_t)MTOT * DMODEL];
__device__ float g_o[(size_t)MTOT * DMODEL];

// ---------------- SGEMM: C[M,N] = A[M,K] @ B[N,K]^T  (both K-contiguous) --------
// 128x128 block tile, 256 threads, 8x8 microtile, K-step 8.
__global__ void __launch_bounds__(256) sgemm_nt(const float* __restrict__ A,
                                                const float* __restrict__ Bm,
                                                float* __restrict__ C,
                                                int Md, int Nd, int Kd) {
    __shared__ float As[8][132];
    __shared__ float Bs[8][132];

    const int t  = threadIdx.x;
    const int m0 = blockIdx.y * 128;
    const int n0 = blockIdx.x * 128;

    const int lrow = t >> 1;          // 0..127
    const int lk   = (t & 1) * 4;     // 0 or 4

    const float* Aptr = A + (size_t)(m0 + lrow) * Kd + lk;
    const float* Bptr = Bm + (size_t)(n0 + lrow) * Kd + lk;

    const int rr = t >> 4;            // 0..15  (row group)
    const int cc = t & 15;            // 0..15  (col group)

    float acc[8][8];
#pragma unroll
    for (int i = 0; i < 8; i++)
#pragma unroll
        for (int j = 0; j < 8; j++) acc[i][j] = 0.f;

    for (int k0 = 0; k0 < Kd; k0 += 8) {
        float4 av = *(const float4*)(Aptr + k0);
        float4 bv = *(const float4*)(Bptr + k0);
        __syncthreads();
        As[lk + 0][lrow] = av.x; As[lk + 1][lrow] = av.y;
        As[lk + 2][lrow] = av.z; As[lk + 3][lrow] = av.w;
        Bs[lk + 0][lrow] = bv.x; Bs[lk + 1][lrow] = bv.y;
        Bs[lk + 2][lrow] = bv.z; Bs[lk + 3][lrow] = bv.w;
        __syncthreads();

#pragma unroll
        for (int kk = 0; kk < 8; kk++) {
            float4 a0 = *(const float4*)&As[kk][rr * 4];
            float4 a1 = *(const float4*)&As[kk][rr * 4 + 64];
            float4 b0 = *(const float4*)&Bs[kk][cc * 4];
            float4 b1 = *(const float4*)&Bs[kk][cc * 4 + 64];
            float a[8] = {a0.x, a0.y, a0.z, a0.w, a1.x, a1.y, a1.z, a1.w};
            float b[8] = {b0.x, b0.y, b0.z, b0.w, b1.x, b1.y, b1.z, b1.w};
#pragma unroll
            for (int i = 0; i < 8; i++)
#pragma unroll
                for (int j = 0; j < 8; j++) acc[i][j] += a[i] * b[j];
        }
    }

#pragma unroll
    for (int rg = 0; rg < 2; rg++) {
#pragma unroll
        for (int i = 0; i < 4; i++) {
            int m = m0 + rg * 64 + rr * 4 + i;
            float* crow = C + (size_t)m * Nd + n0;
            float4 v0 = make_float4(acc[rg * 4 + i][0], acc[rg * 4 + i][1],
                                    acc[rg * 4 + i][2], acc[rg * 4 + i][3]);
            float4 v1 = make_float4(acc[rg * 4 + i][4], acc[rg * 4 + i][5],
                                    acc[rg * 4 + i][6], acc[rg * 4 + i][7]);
            *(float4*)(crow + cc * 4)      = v0;
            *(float4*)(crow + 64 + cc * 4) = v1;
        }
    }
}

// ---------------- RoPE (in-place over (B,S,H,DHEAD)) ----------------------------
__global__ void rope_kernel(float* __restrict__ tdata) {
    int idx = blockIdx.x * blockDim.x + threadIdx.x;   // pair index
    const int pairs_per_head = DHEAD / 2;              // 64
    const int total = B_SZ * SEQ * NHEAD * pairs_per_head;
    if (idx >= total) return;
    int i = idx % pairs_per_head;
    int h = (idx / pairs_per_head) % NHEAD;
    int s = (idx / (pairs_per_head * NHEAD)) % SEQ;
    int b = idx / (pairs_per_head * NHEAD * SEQ);

    float inv_freq = powf(10000.0f, -(float)(2 * i) / (float)DHEAD);
    float ang = (float)s * inv_freq;
    float sn, cs;
    sincosf(ang, &sn, &cs);

    float* base = tdata + ((size_t)(b * SEQ + s)) * DMODEL + h * DHEAD + 2 * i;
    float e = base[0];
    float o = base[1];
    base[0] = e * cs - o * sn;
    base[1] = e * sn + o * cs;
}

// ---------------- Flash attention (causal) --------------------------------------
// BM=64 queries, BN=64 keys per step, 256 threads.
// thread t: r = t/4 (query row in tile), c = t%4 (owns dims c*32 .. c*32+31).
#define FA_BM 64
#define FA_BN 64
#define FA_SMEM ((2 * FA_BN * DHEAD + FA_BM * (FA_BN + 1)) * 4)

__global__ void __launch_bounds__(256) flash_attn(const float* __restrict__ Q,
                                                  const float* __restrict__ Kt,
                                                  const float* __restrict__ V,
                                                  float* __restrict__ O) {
    extern __shared__ float sm[];
    float* Ks = sm;                       // [FA_BN][128]
    float* Vs = sm + FA_BN * DHEAD;       // [FA_BN][128]
    float* Ss = sm + 2 * FA_BN * DHEAD;   // [FA_BM][FA_BN+1]

    const int q0 = blockIdx.x * FA_BM;
    const int h  = blockIdx.y;
    const int b  = blockIdx.z;
    const int t  = threadIdx.x;
    const int r  = t >> 2;
    const int c  = t & 3;
    const int lane = t & 31;

    const float scale = 0.08838834764831845f;  // 1/sqrt(128)

    // load my Q fragment (pre-scaled)
    float qreg[32];
    {
        const float* qrow = Q + ((size_t)(b * SEQ + q0 + r)) * DMODEL + h * DHEAD + c * 32;
#pragma unroll
        for (int j = 0; j < 32; j += 4) {
            float4 v4 = *(const float4*)(qrow + j);
            qreg[j] = v4.x * scale; qreg[j + 1] = v4.y * scale;
            qreg[j + 2] = v4.z * scale; qreg[j + 3] = v4.w * scale;
        }
    }

    float acc[32];
#pragma unroll
    for (int d = 0; d < 32; d++) acc[d] = 0.f;
    float m_i = -1e30f, l_i = 0.f;

    for (int k0 = 0; k0 < q0 + FA_BM; k0 += FA_BN) {
        __syncthreads();  // protect previous tiles
        // stage K and V tiles (64x128 each)
        for (int i = t; i < FA_BN * DHEAD / 4; i += 256) {
            int row = i >> 5;
            int col = i & 31;
            const float* krow = Kt + ((size_t)(b * SEQ + k0 + row)) * DMODEL + h * DHEAD;
            const float* vrow = V + ((size_t)(b * SEQ + k0 + row)) * DMODEL + h * DHEAD;
            ((float4*)Ks)[i] = ((const float4*)krow)[col];
            ((float4*)Vs)[i] = ((const float4*)vrow)[col];
        }
        __syncthreads();

        // ---- scores for my row r ----
        float mx = -1e30f;
        for (int j = 0; j < FA_BN; j++) {
            const float* krow = &Ks[j * DHEAD + c * 32];
            float p = 0.f;
#pragma unroll
            for (int jj = 0; jj < 32; jj += 4) {
                float4 kv = *(const float4*)(krow + jj);
                p += qreg[jj] * kv.x + qreg[jj + 1] * kv.y +
                     qreg[jj + 2] * kv.z + qreg[jj + 3] * kv.w;
            }
            p += __shfl_xor_sync(0xffffffffu, p, 1);
            p += __shfl_xor_sync(0xffffffffu, p, 2);
            if (k0 + j > q0 + r) p = -1e30f;          // causal mask
            if (c == 0) Ss[r * (FA_BN + 1) + j] = p;
            mx = fmaxf(mx, p);
        }

        float m_new = fmaxf(m_i, mx);
        float alpha = __expf(m_i - m_new);

        // exp pass done by c==0 lane of each row (avoids read/write race)
        float lsum = 0.f;
        __syncwarp();
        if (c == 0) {
            for (int j = 0; j < FA_BN; j++) {
                float p = Ss[r * (FA_BN + 1) + j];
                float e = __expf(p - m_new);
                Ss[r * (FA_BN + 1) + j] = e;
                lsum += e;
            }
        }
        __syncwarp();
        lsum = __shfl_sync(0xffffffffu, lsum, lane & ~3);

        l_i = l_i * alpha + lsum;
#pragma unroll
        for (int d = 0; d < 32; d++) acc[d] *= alpha;

        // ---- P @ V ----
        for (int j = 0; j < FA_BN; j++) {
            float pj = Ss[r * (FA_BN + 1) + j];
            const float* vrow = &Vs[j * DHEAD + c * 32];
#pragma unroll
            for (int d = 0; d < 32; d += 4) {
                float4 vv = *(const float4*)(vrow + d);
                acc[d]     += pj * vv.x;
                acc[d + 1] += pj * vv.y;
                acc[d + 2] += pj * vv.z;
                acc[d + 3] += pj * vv.w;
            }
        }
        m_i = m_new;
    }

    // write out
    float inv_l = 1.0f / l_i;
    float* orow = O + ((size_t)(b * SEQ + q0 + r)) * DMODEL + h * DHEAD + c * 32;
#pragma unroll
    for (int d = 0; d < 32; d += 4) {
        float4 v4 = make_float4(acc[d] * inv_l, acc[d + 1] * inv_l,
                                acc[d + 2] * inv_l, acc[d + 3] * inv_l);
        *(float4*)(orow + d) = v4;
    }
}

// ---------------- launch --------------------------------------------------------
extern "C" void kernel_launch(void* const* d_in, const int* in_sizes, int n_in,
                              void* d_out, int out_size) {
    const float* x  = (const float*)d_in[0];
    const float* wq = (const float*)d_in[1];
    const float* wk = (const float*)d_in[2];
    const float* wv = (const float*)d_in[3];
    const float* wo = (const float*)d_in[4];
    float* out = (float*)d_out;

    float *q, *k, *v, *o;
    cudaGetSymbolAddress((void**)&q, g_q);
    cudaGetSymbolAddress((void**)&k, g_k);
    cudaGetSymbolAddress((void**)&v, g_v);
    cudaGetSymbolAddress((void**)&o, g_o);

    dim3 gg(DMODEL / 128, MTOT / 128);

    sgemm_nt<<<gg, 256>>>(x, wq, q, MTOT, DMODEL, DMODEL);
    sgemm_nt<<<gg, 256>>>(x, wk, k, MTOT, DMODEL, DMODEL);
    sgemm_nt<<<gg, 256>>>(x, wv, v, MTOT, DMODEL, DMODEL);

    int rope_total = B_SZ * SEQ * NHEAD * (DHEAD / 2);
    rope_kernel<<<(rope_total + 255) / 256, 256>>>(q);
    rope_kernel<<<(rope_total + 255) / 256, 256>>>(k);

    cudaFuncSetAttribute(flash_attn, cudaFuncAttributeMaxDynamicSharedMemorySize, FA_SMEM);
    flash_attn<<<dim3(SEQ / FA_BM, NHEAD, B_SZ), 256, FA_SMEM>>>(q, k, v, o);

    sgemm_nt<<<gg, 256>>>(o, wo, out, MTOT, DMODEL, DMODEL);
}

// round 3
// speedup vs baseline: 1.1513x; 1.1513x over previous
#include <cuda_runtime.h>
#include <cuda_bf16.h>
#include <math.h>
#include <stdint.h>

// Problem constants
#define B_SZ 2
#define SEQ 2048
#define DMODEL 2048
#define NHEAD 16
#define DHEAD 128
#define MTOT (B_SZ * SEQ)   // 4096

// ---------------- scratch (device globals; no allocation allowed) ---------------
__device__ float g_q[(size_t)MTOT * DMODEL];
__device__ float g_k[(size_t)MTOT * DMODEL];
__device__ float g_v[(size_t)MTOT * DMODEL];
__device__ float g_o[(size_t)MTOT * DMODEL];

__device__ __nv_bfloat16 g_xh[(size_t)MTOT * DMODEL];
__device__ __nv_bfloat16 g_xl[(size_t)MTOT * DMODEL];
__device__ __nv_bfloat16 g_oh[(size_t)MTOT * DMODEL];
__device__ __nv_bfloat16 g_ol[(size_t)MTOT * DMODEL];
__device__ __nv_bfloat16 g_wqh[(size_t)DMODEL * DMODEL];
__device__ __nv_bfloat16 g_wql[(size_t)DMODEL * DMODEL];
__device__ __nv_bfloat16 g_wkh[(size_t)DMODEL * DMODEL];
__device__ __nv_bfloat16 g_wkl[(size_t)DMODEL * DMODEL];
__device__ __nv_bfloat16 g_wvh[(size_t)DMODEL * DMODEL];
__device__ __nv_bfloat16 g_wvl[(size_t)DMODEL * DMODEL];
__device__ __nv_bfloat16 g_woh[(size_t)DMODEL * DMODEL];
__device__ __nv_bfloat16 g_wol[(size_t)DMODEL * DMODEL];

// ================= helpers ======================================================
__device__ __forceinline__ uint32_t smem_to_u32(const void* p) {
    uint32_t a;
    asm("{ .reg .u64 t; cvta.to.shared.u64 t, %1; cvt.u32.u64 %0, t; }" : "=r"(a) : "l"(p));
    return a;
}
#define CP_ASYNC16(dst, src) \
    asm volatile("cp.async.cg.shared.global [%0], [%1], 16;" :: "r"(dst), "l"(src) : "memory")
#define CP_COMMIT() asm volatile("cp.async.commit_group;" ::: "memory")
#define CP_WAIT(n)  asm volatile("cp.async.wait_group %0;" :: "n"(n) : "memory")

__device__ __forceinline__ void ldsm_x4(uint32_t& r0, uint32_t& r1, uint32_t& r2, uint32_t& r3,
                                        uint32_t addr) {
    asm volatile("ldmatrix.sync.aligned.m8n8.x4.shared.b16 {%0,%1,%2,%3}, [%4];"
                 : "=r"(r0), "=r"(r1), "=r"(r2), "=r"(r3) : "r"(addr));
}
__device__ __forceinline__ void mma_bf16(float* c, const uint32_t* a, const uint32_t* b) {
    asm volatile(
        "mma.sync.aligned.m16n8k16.row.col.f32.bf16.bf16.f32 "
        "{%0,%1,%2,%3}, {%4,%5,%6,%7}, {%8,%9}, {%0,%1,%2,%3};"
        : "+f"(c[0]), "+f"(c[1]), "+f"(c[2]), "+f"(c[3])
        : "r"(a[0]), "r"(a[1]), "r"(a[2]), "r"(a[3]), "r"(b[0]), "r"(b[1]));
}

// ================= fp32 -> bf16 hi/lo split =====================================
__global__ void __launch_bounds__(256) split_bf16(const float* __restrict__ in,
                                                  __nv_bfloat16* __restrict__ hi,
                                                  __nv_bfloat16* __restrict__ lo,
                                                  int n4) {
    int i = blockIdx.x * blockDim.x + threadIdx.x;
    if (i >= n4) return;
    float4 v = ((const float4*)in)[i];
    __nv_bfloat16 h0 = __float2bfloat16_rn(v.x);
    __nv_bfloat16 h1 = __float2bfloat16_rn(v.y);
    __nv_bfloat16 h2 = __float2bfloat16_rn(v.z);
    __nv_bfloat16 h3 = __float2bfloat16_rn(v.w);
    __nv_bfloat16 l0 = __float2bfloat16_rn(v.x - __bfloat162float(h0));
    __nv_bfloat16 l1 = __float2bfloat16_rn(v.y - __bfloat162float(h1));
    __nv_bfloat16 l2 = __float2bfloat16_rn(v.z - __bfloat162float(h2));
    __nv_bfloat16 l3 = __float2bfloat16_rn(v.w - __bfloat162float(h3));
    ((__nv_bfloat162*)hi)[2 * i]     = __nv_bfloat162(h0, h1);
    ((__nv_bfloat162*)hi)[2 * i + 1] = __nv_bfloat162(h2, h3);
    ((__nv_bfloat162*)lo)[2 * i]     = __nv_bfloat162(l0, l1);
    ((__nv_bfloat162*)lo)[2 * i + 1] = __nv_bfloat162(l2, l3);
}

// ================= HMMA GEMM: C[M,N] = A[M,K] @ B[N,K]^T ========================
// 128x128 CTA tile, 8 warps (64x32 warp tiles), K-chunk 32, cp.async double buffer.
// SMEM rows use 80-byte pitch (40 bf16): r*80 mod 128 -> disjoint 16B spans,
// conflict-free ldmatrix.
#define GBM 128
#define GBN 128
#define GBK 32
#define PITCHB 80                       // bytes per smem row
#define TILE_B (128 * PITCHB)           // 10240 bytes, one operand tile
#define STAGE_B (4 * TILE_B)            // Ah, Al, Bh, Bl
#define GSMEM (2 * STAGE_B)             // 81920

__global__ void __launch_bounds__(256) gemm_hmma(const __nv_bfloat16* __restrict__ Ah,
                                                 const __nv_bfloat16* __restrict__ Al,
                                                 const __nv_bfloat16* __restrict__ Bh,
                                                 const __nv_bfloat16* __restrict__ Bl,
                                                 float* __restrict__ C,
                                                 int Md, int Nd, int Kd) {
    extern __shared__ char smem[];
    const uint32_t sbase = smem_to_u32(smem);
    const int tid = threadIdx.x;
    const int wid = tid >> 5;
    const int lid = tid & 31;
    const int m0 = blockIdx.y * GBM;
    const int n0 = blockIdx.x * GBN;

    const int wm = (wid >> 2) * 64;     // warp m-offset in tile
    const int wn = (wid & 3) * 32;      // warp n-offset in tile

    // ldmatrix lane address components (16-row x 16-col tile):
    const int lrow = (lid & 7) + ((lid >> 3) & 1) * 8;
    const int lcolb = ((lid >> 4) & 1) * 16;   // byte offset (8 bf16)

    const __nv_bfloat16* srcs[4] = {
        Ah + (size_t)m0 * Kd, Al + (size_t)m0 * Kd,
        Bh + (size_t)n0 * Kd, Bl + (size_t)n0 * Kd };

    // per-thread load assignment: 8 x cp.async per stage
    // idx = j*256 + tid; tile = idx>>9, row = (idx>>2)&127, chunk16 = idx&3
    const int nchunk = Kd / GBK;   // 64

    float acc[4][4][4];
#pragma unroll
    for (int a = 0; a < 4; a++)
#pragma unroll
        for (int b = 0; b < 4; b++)
#pragma unroll
            for (int cc = 0; cc < 4; cc++) acc[a][b][cc] = 0.f;

    auto issue_loads = [&](int c) {
        const int buf = c & 1;
        const uint32_t so = sbase + buf * STAGE_B;
        const int kc = c * GBK;
#pragma unroll
        for (int j = 0; j < 8; j++) {
            int idx = j * 256 + tid;
            int tile = idx >> 9;
            int row = (idx >> 2) & 127;
            int ck = idx & 3;
            const __nv_bfloat16* src = srcs[tile] + (size_t)row * Kd + kc + ck * 8;
            uint32_t dst = so + tile * TILE_B + row * PITCHB + ck * 16;
            CP_ASYNC16(dst, src);
        }
        CP_COMMIT();
    };

    issue_loads(0);

    for (int c = 0; c < nchunk; c++) {
        const int buf = c & 1;
        if (c + 1 < nchunk) {
            issue_loads(c + 1);
            CP_WAIT(1);
        } else {
            CP_WAIT(0);
        }
        __syncthreads();

        const uint32_t so = sbase + buf * STAGE_B;
        const uint32_t t_ah = so + 0 * TILE_B;
        const uint32_t t_al = so + 1 * TILE_B;
        const uint32_t t_bh = so + 2 * TILE_B;
        const uint32_t t_bl = so + 3 * TILE_B;

#pragma unroll
        for (int kk = 0; kk < 2; kk++) {          // two k16 steps per chunk
            const uint32_t kb = kk * 32 + lcolb;  // byte col offset

            // B fragments: 2 x ldmatrix.x4 per operand (covers 32 n-rows)
            uint32_t bh[4][2], bl[4][2];
#pragma unroll
            for (int g = 0; g < 2; g++) {
                uint32_t addr = t_bh + (wn + g * 16 + lrow) * PITCHB + kb;
                uint32_t r0, r1, r2, r3;
                ldsm_x4(r0, r1, r2, r3, addr);
                bh[g * 2 + 0][0] = r0; bh[g * 2 + 0][1] = r2;
                bh[g * 2 + 1][0] = r1; bh[g * 2 + 1][1] = r3;
                addr = t_bl + (wn + g * 16 + lrow) * PITCHB + kb;
                ldsm_x4(r0, r1, r2, r3, addr);
                bl[g * 2 + 0][0] = r0; bl[g * 2 + 0][1] = r2;
                bl[g * 2 + 1][0] = r1; bl[g * 2 + 1][1] = r3;
            }

#pragma unroll
            for (int mt = 0; mt < 4; mt++) {
                uint32_t ah[4], al[4];
                uint32_t addr = t_ah + (wm + mt * 16 + lrow) * PITCHB + kb;
                ldsm_x4(ah[0], ah[1], ah[2], ah[3], addr);
                addr = t_al + (wm + mt * 16 + lrow) * PITCHB + kb;
                ldsm_x4(al[0], al[1], al[2], al[3], addr);
#pragma unroll
                for (int nt = 0; nt < 4; nt++) {
                    mma_bf16(acc[mt][nt], ah, bh[nt]);
                    mma_bf16(acc[mt][nt], ah, bl[nt]);
                    mma_bf16(acc[mt][nt], al, bh[nt]);
                }
            }
        }
        __syncthreads();
    }

    // epilogue: acc tile (16x8) layout: c0,c1 -> row l/4, cols (l%4)*2, c2,c3 -> row+8
    const int er = lid >> 2;
    const int ec = (lid & 3) * 2;
#pragma unroll
    for (int mt = 0; mt < 4; mt++) {
#pragma unroll
        for (int nt = 0; nt < 4; nt++) {
            int m = m0 + wm + mt * 16 + er;
            int n = n0 + wn + nt * 8 + ec;
            float2* p0 = (float2*)&C[(size_t)m * Nd + n];
            float2* p1 = (float2*)&C[(size_t)(m + 8) * Nd + n];
            *p0 = make_float2(acc[mt][nt][0], acc[mt][nt][1]);
            *p1 = make_float2(acc[mt][nt][2], acc[mt][nt][3]);
        }
    }
}

// ---------------- RoPE (in-place over (B,S,H,DHEAD)) ----------------------------
__global__ void rope_kernel(float* __restrict__ tdata) {
    int idx = blockIdx.x * blockDim.x + threadIdx.x;   // pair index
    const int pairs_per_head = DHEAD / 2;              // 64
    const int total = B_SZ * SEQ * NHEAD * pairs_per_head;
    if (idx >= total) return;
    int i = idx % pairs_per_head;
    int h = (idx / pairs_per_head) % NHEAD;
    int s = (idx / (pairs_per_head * NHEAD)) % SEQ;
    int b = idx / (pairs_per_head * NHEAD * SEQ);

    float inv_freq = powf(10000.0f, -(float)(2 * i) / (float)DHEAD);
    float ang = (float)s * inv_freq;
    float sn, cs;
    sincosf(ang, &sn, &cs);

    float* base = tdata + ((size_t)(b * SEQ + s)) * DMODEL + h * DHEAD + 2 * i;
    float e = base[0];
    float o = base[1];
    base[0] = e * cs - o * sn;
    base[1] = e * sn + o * cs;
}

// ---------------- Flash attention (causal), fp32 SIMT ---------------------------
#define FA_BM 64
#define FA_BN 64
#define FA_SMEM ((2 * FA_BN * DHEAD + FA_BM * (FA_BN + 1)) * 4)

__global__ void __launch_bounds__(256) flash_attn(const float* __restrict__ Q,
                                                  const float* __restrict__ Kt,
                                                  const float* __restrict__ V,
                                                  float* __restrict__ O) {
    extern __shared__ float sm[];
    float* Ks = sm;                       // [FA_BN][128]
    float* Vs = sm + FA_BN * DHEAD;       // [FA_BN][128]
    float* Ss = sm + 2 * FA_BN * DHEAD;   // [FA_BM][FA_BN+1]

    const int q0 = blockIdx.x * FA_BM;
    const int h  = blockIdx.y;
    const int b  = blockIdx.z;
    const int t  = threadIdx.x;
    const int r  = t >> 2;
    const int c  = t & 3;
    const int lane = t & 31;

    const float scale = 0.08838834764831845f;  // 1/sqrt(128)

    float qreg[32];
    {
        const float* qrow = Q + ((size_t)(b * SEQ + q0 + r)) * DMODEL + h * DHEAD + c * 32;
#pragma unroll
        for (int j = 0; j < 32; j += 4) {
            float4 v4 = *(const float4*)(qrow + j);
            qreg[j] = v4.x * scale; qreg[j + 1] = v4.y * scale;
            qreg[j + 2] = v4.z * scale; qreg[j + 3] = v4.w * scale;
        }
    }

    float acc[32];
#pragma unroll
    for (int d = 0; d < 32; d++) acc[d] = 0.f;
    float m_i = -1e30f, l_i = 0.f;

    for (int k0 = 0; k0 < q0 + FA_BM; k0 += FA_BN) {
        __syncthreads();
        for (int i = t; i < FA_BN * DHEAD / 4; i += 256) {
            int row = i >> 5;
            int col = i & 31;
            const float* krow = Kt + ((size_t)(b * SEQ + k0 + row)) * DMODEL + h * DHEAD;
            const float* vrow = V + ((size_t)(b * SEQ + k0 + row)) * DMODEL + h * DHEAD;
            ((float4*)Ks)[i] = ((const float4*)krow)[col];
            ((float4*)Vs)[i] = ((const float4*)vrow)[col];
        }
        __syncthreads();

        float mx = -1e30f;
        for (int j = 0; j < FA_BN; j++) {
            const float* krow = &Ks[j * DHEAD + c * 32];
            float p = 0.f;
#pragma unroll
            for (int jj = 0; jj < 32; jj += 4) {
                float4 kv = *(const float4*)(krow + jj);
                p += qreg[jj] * kv.x + qreg[jj + 1] * kv.y +
                     qreg[jj + 2] * kv.z + qreg[jj + 3] * kv.w;
            }
            p += __shfl_xor_sync(0xffffffffu, p, 1);
            p += __shfl_xor_sync(0xffffffffu, p, 2);
            if (k0 + j > q0 + r) p = -1e30f;
            if (c == 0) Ss[r * (FA_BN + 1) + j] = p;
            mx = fmaxf(mx, p);
        }

        float m_new = fmaxf(m_i, mx);
        float alpha = __expf(m_i - m_new);

        float lsum = 0.f;
        __syncwarp();
        if (c == 0) {
            for (int j = 0; j < FA_BN; j++) {
                float p = Ss[r * (FA_BN + 1) + j];
                float e = __expf(p - m_new);
                Ss[r * (FA_BN + 1) + j] = e;
                lsum += e;
            }
        }
        __syncwarp();
        lsum = __shfl_sync(0xffffffffu, lsum, lane & ~3);

        l_i = l_i * alpha + lsum;
#pragma unroll
        for (int d = 0; d < 32; d++) acc[d] *= alpha;

        for (int j = 0; j < FA_BN; j++) {
            float pj = Ss[r * (FA_BN + 1) + j];
            const float* vrow = &Vs[j * DHEAD + c * 32];
#pragma unroll
            for (int d = 0; d < 32; d += 4) {
                float4 vv = *(const float4*)(vrow + d);
                acc[d]     += pj * vv.x;
                acc[d + 1] += pj * vv.y;
                acc[d + 2] += pj * vv.z;
                acc[d + 3] += pj * vv.w;
            }
        }
        m_i = m_new;
    }

    float inv_l = 1.0f / l_i;
    float* orow = O + ((size_t)(b * SEQ + q0 + r)) * DMODEL + h * DHEAD + c * 32;
#pragma unroll
    for (int d = 0; d < 32; d += 4) {
        float4 v4 = make_float4(acc[d] * inv_l, acc[d + 1] * inv_l,
                                acc[d + 2] * inv_l, acc[d + 3] * inv_l);
        *(float4*)(orow + d) = v4;
    }
}

// ---------------- launch --------------------------------------------------------
extern "C" void kernel_launch(void* const* d_in, const int* in_sizes, int n_in,
                              void* d_out, int out_size) {
    const float* x  = (const float*)d_in[0];
    const float* wq = (const float*)d_in[1];
    const float* wk = (const float*)d_in[2];
    const float* wv = (const float*)d_in[3];
    const float* wo = (const float*)d_in[4];
    float* out = (float*)d_out;

    float *q, *k, *v, *o;
    cudaGetSymbolAddress((void**)&q, g_q);
    cudaGetSymbolAddress((void**)&k, g_k);
    cudaGetSymbolAddress((void**)&v, g_v);
    cudaGetSymbolAddress((void**)&o, g_o);
    __nv_bfloat16 *xh, *xl, *oh, *ol, *wqh, *wql, *wkh, *wkl, *wvh, *wvl, *woh, *wol;
    cudaGetSymbolAddress((void**)&xh, g_xh);   cudaGetSymbolAddress((void**)&xl, g_xl);
    cudaGetSymbolAddress((void**)&oh, g_oh);   cudaGetSymbolAddress((void**)&ol, g_ol);
    cudaGetSymbolAddress((void**)&wqh, g_wqh); cudaGetSymbolAddress((void**)&wql, g_wql);
    cudaGetSymbolAddress((void**)&wkh, g_wkh); cudaGetSymbolAddress((void**)&wkl, g_wkl);
    cudaGetSymbolAddress((void**)&wvh, g_wvh); cudaGetSymbolAddress((void**)&wvl, g_wvl);
    cudaGetSymbolAddress((void**)&woh, g_woh); cudaGetSymbolAddress((void**)&wol, g_wol);

    const int NX4 = MTOT * DMODEL / 4;     // 2097152
    const int NW4 = DMODEL * DMODEL / 4;   // 1048576

    split_bf16<<<NX4 / 256, 256>>>(x,  xh,  xl,  NX4);
    split_bf16<<<NW4 / 256, 256>>>(wq, wqh, wql, NW4);
    split_bf16<<<NW4 / 256, 256>>>(wk, wkh, wkl, NW4);
    split_bf16<<<NW4 / 256, 256>>>(wv, wvh, wvl, NW4);
    split_bf16<<<NW4 / 256, 256>>>(wo, woh, wol, NW4);

    cudaFuncSetAttribute(gemm_hmma, cudaFuncAttributeMaxDynamicSharedMemorySize, GSMEM);
    dim3 gg(DMODEL / GBN, MTOT / GBM);     // (16, 32)
    gemm_hmma<<<gg, 256, GSMEM>>>(xh, xl, wqh, wql, q, MTOT, DMODEL, DMODEL);
    gemm_hmma<<<gg, 256, GSMEM>>>(xh, xl, wkh, wkl, k, MTOT, DMODEL, DMODEL);
    gemm_hmma<<<gg, 256, GSMEM>>>(xh, xl, wvh, wvl, v, MTOT, DMODEL, DMODEL);

    int rope_total = B_SZ * SEQ * NHEAD * (DHEAD / 2);
    rope_kernel<<<(rope_total + 255) / 256, 256>>>(q);
    rope_kernel<<<(rope_total + 255) / 256, 256>>>(k);

    cudaFuncSetAttribute(flash_attn, cudaFuncAttributeMaxDynamicSharedMemorySize, FA_SMEM);
    flash_attn<<<dim3(SEQ / FA_BM, NHEAD, B_SZ), 256, FA_SMEM>>>(q, k, v, o);

    split_bf16<<<NX4 / 256, 256>>>(o, oh, ol, NX4);
    gemm_hmma<<<gg, 256, GSMEM>>>(oh, ol, woh, wol, out, MTOT, DMODEL, DMODEL);
}

// round 4
// speedup vs baseline: 6.4259x; 5.5815x over previous
#include <cuda_runtime.h>
#include <cuda_bf16.h>
#include <math.h>
#include <stdint.h>

// Problem constants
#define B_SZ 2
#define SEQ 2048
#define DMODEL 2048
#define NHEAD 16
#define DHEAD 128
#define MTOT (B_SZ * SEQ)   // 4096

// ---------------- scratch (device globals; no allocation allowed) ---------------
__device__ float g_q[(size_t)MTOT * DMODEL];
__device__ float g_k[(size_t)MTOT * DMODEL];
__device__ float g_v[(size_t)MTOT * DMODEL];
__device__ float g_o[(size_t)MTOT * DMODEL];

__device__ __nv_bfloat16 g_xh[(size_t)MTOT * DMODEL];
__device__ __nv_bfloat16 g_xl[(size_t)MTOT * DMODEL];
__device__ __nv_bfloat16 g_oh[(size_t)MTOT * DMODEL];
__device__ __nv_bfloat16 g_ol[(size_t)MTOT * DMODEL];
__device__ __nv_bfloat16 g_kh[(size_t)MTOT * DMODEL];
__device__ __nv_bfloat16 g_kl[(size_t)MTOT * DMODEL];
__device__ __nv_bfloat16 g_vh[(size_t)MTOT * DMODEL];
__device__ __nv_bfloat16 g_vl[(size_t)MTOT * DMODEL];
__device__ __nv_bfloat16 g_wqh[(size_t)DMODEL * DMODEL];
__device__ __nv_bfloat16 g_wql[(size_t)DMODEL * DMODEL];
__device__ __nv_bfloat16 g_wkh[(size_t)DMODEL * DMODEL];
__device__ __nv_bfloat16 g_wkl[(size_t)DMODEL * DMODEL];
__device__ __nv_bfloat16 g_wvh[(size_t)DMODEL * DMODEL];
__device__ __nv_bfloat16 g_wvl[(size_t)DMODEL * DMODEL];
__device__ __nv_bfloat16 g_woh[(size_t)DMODEL * DMODEL];
__device__ __nv_bfloat16 g_wol[(size_t)DMODEL * DMODEL];

// ================= helpers ======================================================
__device__ __forceinline__ uint32_t smem_to_u32(const void* p) {
    uint32_t a;
    asm("{ .reg .u64 t; cvta.to.shared.u64 t, %1; cvt.u32.u64 %0, t; }" : "=r"(a) : "l"(p));
    return a;
}
#define CP_ASYNC16(dst, src) \
    asm volatile("cp.async.cg.shared.global [%0], [%1], 16;" :: "r"(dst), "l"(src) : "memory")
#define CP_COMMIT() asm volatile("cp.async.commit_group;" ::: "memory")
#define CP_WAIT(n)  asm volatile("cp.async.wait_group %0;" :: "n"(n) : "memory")

__device__ __forceinline__ void ldsm_x4(uint32_t& r0, uint32_t& r1, uint32_t& r2, uint32_t& r3,
                                        uint32_t addr) {
    asm volatile("ldmatrix.sync.aligned.m8n8.x4.shared.b16 {%0,%1,%2,%3}, [%4];"
                 : "=r"(r0), "=r"(r1), "=r"(r2), "=r"(r3) : "r"(addr));
}
__device__ __forceinline__ void ldsm_x4_t(uint32_t& r0, uint32_t& r1, uint32_t& r2, uint32_t& r3,
                                          uint32_t addr) {
    asm volatile("ldmatrix.sync.aligned.m8n8.x4.trans.shared.b16 {%0,%1,%2,%3}, [%4];"
                 : "=r"(r0), "=r"(r1), "=r"(r2), "=r"(r3) : "r"(addr));
}
__device__ __forceinline__ void mma_bf16(float* c, const uint32_t* a, const uint32_t* b) {
    asm volatile(
        "mma.sync.aligned.m16n8k16.row.col.f32.bf16.bf16.f32 "
        "{%0,%1,%2,%3}, {%4,%5,%6,%7}, {%8,%9}, {%0,%1,%2,%3};"
        : "+f"(c[0]), "+f"(c[1]), "+f"(c[2]), "+f"(c[3])
        : "r"(a[0]), "r"(a[1]), "r"(a[2]), "r"(a[3]), "r"(b[0]), "r"(b[1]));
}
__device__ __forceinline__ uint32_t pack_bf16x2(float lo, float hi) {
    uint32_t r;
    asm("cvt.rn.bf16x2.f32 %0, %1, %2;" : "=r"(r) : "f"(hi), "f"(lo));
    return r;
}

// ================= fp32 -> bf16 hi/lo split =====================================
__global__ void __launch_bounds__(256) split_bf16(const float* __restrict__ in,
                                                  __nv_bfloat16* __restrict__ hi,
                                                  __nv_bfloat16* __restrict__ lo,
                                                  int n4) {
    int i = blockIdx.x * blockDim.x + threadIdx.x;
    if (i >= n4) return;
    float4 v = ((const float4*)in)[i];
    __nv_bfloat16 h0 = __float2bfloat16_rn(v.x);
    __nv_bfloat16 h1 = __float2bfloat16_rn(v.y);
    __nv_bfloat16 h2 = __float2bfloat16_rn(v.z);
    __nv_bfloat16 h3 = __float2bfloat16_rn(v.w);
    __nv_bfloat16 l0 = __float2bfloat16_rn(v.x - __bfloat162float(h0));
    __nv_bfloat16 l1 = __float2bfloat16_rn(v.y - __bfloat162float(h1));
    __nv_bfloat16 l2 = __float2bfloat16_rn(v.z - __bfloat162float(h2));
    __nv_bfloat16 l3 = __float2bfloat16_rn(v.w - __bfloat162float(h3));
    ((__nv_bfloat162*)hi)[2 * i]     = __nv_bfloat162(h0, h1);
    ((__nv_bfloat162*)hi)[2 * i + 1] = __nv_bfloat162(h2, h3);
    ((__nv_bfloat162*)lo)[2 * i]     = __nv_bfloat162(l0, l1);
    ((__nv_bfloat162*)lo)[2 * i + 1] = __nv_bfloat162(l2, l3);
}

// ================= HMMA GEMM: C[M,N] = A[M,K] @ B[N,K]^T ========================
#define GBM 128
#define GBN 128
#define GBK 32
#define PITCHB 80
#define TILE_B (128 * PITCHB)
#define STAGE_B (4 * TILE_B)
#define GSMEM (2 * STAGE_B)

__global__ void __launch_bounds__(256) gemm_hmma(const __nv_bfloat16* __restrict__ Ah,
                                                 const __nv_bfloat16* __restrict__ Al,
                                                 const __nv_bfloat16* __restrict__ Bh,
                                                 const __nv_bfloat16* __restrict__ Bl,
                                                 float* __restrict__ C,
                                                 int Md, int Nd, int Kd) {
    extern __shared__ char smem[];
    const uint32_t sbase = smem_to_u32(smem);
    const int tid = threadIdx.x;
    const int wid = tid >> 5;
    const int lid = tid & 31;
    const int m0 = blockIdx.y * GBM;
    const int n0 = blockIdx.x * GBN;

    const int wm = (wid >> 2) * 64;
    const int wn = (wid & 3) * 32;

    const int lrow = (lid & 7) + ((lid >> 3) & 1) * 8;
    const int lcolb = ((lid >> 4) & 1) * 16;

    const __nv_bfloat16* srcs[4] = {
        Ah + (size_t)m0 * Kd, Al + (size_t)m0 * Kd,
        Bh + (size_t)n0 * Kd, Bl + (size_t)n0 * Kd };

    const int nchunk = Kd / GBK;

    float acc[4][4][4];
#pragma unroll
    for (int a = 0; a < 4; a++)
#pragma unroll
        for (int b = 0; b < 4; b++)
#pragma unroll
            for (int cc = 0; cc < 4; cc++) acc[a][b][cc] = 0.f;

    auto issue_loads = [&](int c) {
        const int buf = c & 1;
        const uint32_t so = sbase + buf * STAGE_B;
        const int kc = c * GBK;
#pragma unroll
        for (int j = 0; j < 8; j++) {
            int idx = j * 256 + tid;
            int tile = idx >> 9;
            int row = (idx >> 2) & 127;
            int ck = idx & 3;
            const __nv_bfloat16* src = srcs[tile] + (size_t)row * Kd + kc + ck * 8;
            uint32_t dst = so + tile * TILE_B + row * PITCHB + ck * 16;
            CP_ASYNC16(dst, src);
        }
        CP_COMMIT();
    };

    issue_loads(0);

    for (int c = 0; c < nchunk; c++) {
        const int buf = c & 1;
        if (c + 1 < nchunk) {
            issue_loads(c + 1);
            CP_WAIT(1);
        } else {
            CP_WAIT(0);
        }
        __syncthreads();

        const uint32_t so = sbase + buf * STAGE_B;
        const uint32_t t_ah = so + 0 * TILE_B;
        const uint32_t t_al = so + 1 * TILE_B;
        const uint32_t t_bh = so + 2 * TILE_B;
        const uint32_t t_bl = so + 3 * TILE_B;

#pragma unroll
        for (int kk = 0; kk < 2; kk++) {
            const uint32_t kb = kk * 32 + lcolb;

            uint32_t bh[4][2], bl[4][2];
#pragma unroll
            for (int g = 0; g < 2; g++) {
                uint32_t addr = t_bh + (wn + g * 16 + lrow) * PITCHB + kb;
                uint32_t r0, r1, r2, r3;
                ldsm_x4(r0, r1, r2, r3, addr);
                bh[g * 2 + 0][0] = r0; bh[g * 2 + 0][1] = r2;
                bh[g * 2 + 1][0] = r1; bh[g * 2 + 1][1] = r3;
                addr = t_bl + (wn + g * 16 + lrow) * PITCHB + kb;
                ldsm_x4(r0, r1, r2, r3, addr);
                bl[g * 2 + 0][0] = r0; bl[g * 2 + 0][1] = r2;
                bl[g * 2 + 1][0] = r1; bl[g * 2 + 1][1] = r3;
            }

#pragma unroll
            for (int mt = 0; mt < 4; mt++) {
                uint32_t ah[4], al[4];
                uint32_t addr = t_ah + (wm + mt * 16 + lrow) * PITCHB + kb;
                ldsm_x4(ah[0], ah[1], ah[2], ah[3], addr);
                addr = t_al + (wm + mt * 16 + lrow) * PITCHB + kb;
                ldsm_x4(al[0], al[1], al[2], al[3], addr);
#pragma unroll
                for (int nt = 0; nt < 4; nt++) {
                    mma_bf16(acc[mt][nt], ah, bh[nt]);
                    mma_bf16(acc[mt][nt], ah, bl[nt]);
                    mma_bf16(acc[mt][nt], al, bh[nt]);
                }
            }
        }
        __syncthreads();
    }

    const int er = lid >> 2;
    const int ec = (lid & 3) * 2;
#pragma unroll
    for (int mt = 0; mt < 4; mt++) {
#pragma unroll
        for (int nt = 0; nt < 4; nt++) {
            int m = m0 + wm + mt * 16 + er;
            int n = n0 + wn + nt * 8 + ec;
            float2* p0 = (float2*)&C[(size_t)m * Nd + n];
            float2* p1 = (float2*)&C[(size_t)(m + 8) * Nd + n];
            *p0 = make_float2(acc[mt][nt][0], acc[mt][nt][1]);
            *p1 = make_float2(acc[mt][nt][2], acc[mt][nt][3]);
        }
    }
}

// ---------------- RoPE (in-place over (B,S,H,DHEAD)) ----------------------------
__global__ void rope_kernel(float* __restrict__ tdata) {
    int idx = blockIdx.x * blockDim.x + threadIdx.x;
    const int pairs_per_head = DHEAD / 2;
    const int total = B_SZ * SEQ * NHEAD * pairs_per_head;
    if (idx >= total) return;
    int i = idx % pairs_per_head;
    int h = (idx / pairs_per_head) % NHEAD;
    int s = (idx / (pairs_per_head * NHEAD)) % SEQ;
    int b = idx / (pairs_per_head * NHEAD * SEQ);

    float inv_freq = powf(10000.0f, -(float)(2 * i) / (float)DHEAD);
    float ang = (float)s * inv_freq;
    float sn, cs;
    sincosf(ang, &sn, &cs);

    float* base = tdata + ((size_t)(b * SEQ + s)) * DMODEL + h * DHEAD + 2 * i;
    float e = base[0];
    float o = base[1];
    base[0] = e * cs - o * sn;
    base[1] = e * sn + o * cs;
}

// ================= HMMA flash attention (causal) ================================
// CTA: 128 q-rows (8 warps x 16), KV tiles of 64 rows. K/V hi/lo staged in smem
// in 4 d-chunks of [64 rows x 80B pitch] (conflict-free ldmatrix), double-buffered.
#define FBM 128
#define FBN 64
#define FCH (64 * 80)            // one d-chunk: 64 rows x 80B = 5120
#define FARR (4 * FCH)           // one array (kh/kl/vh/vl) = 20480
#define FSTAGE (4 * FARR)        // 81920
#define FSMEM (2 * FSTAGE)       // 163840

__global__ void __launch_bounds__(256) flash_hmma(const float* __restrict__ Qf,
                                                  const __nv_bfloat16* __restrict__ Kh,
                                                  const __nv_bfloat16* __restrict__ Kl,
                                                  const __nv_bfloat16* __restrict__ Vh,
                                                  const __nv_bfloat16* __restrict__ Vl,
                                                  float* __restrict__ O) {
    extern __shared__ char smem[];
    const uint32_t sbase = smem_to_u32(smem);
    const int tid = threadIdx.x;
    const int wid = tid >> 5;
    const int lid = tid & 31;
    const int qb = blockIdx.x;
    const int h  = blockIdx.y;
    const int b  = blockIdx.z;
    const int q0 = qb * FBM;
    const int wm = wid * 16;

    const int lrow  = (lid & 7) + ((lid >> 3) & 1) * 8;
    const int lcolb = ((lid >> 4) & 1) * 16;
    const int r4  = lid >> 2;        // row within 16 (and +8)
    const int c2  = (lid & 3) * 2;   // col pair base

    const float scale = 0.08838834764831845f;   // 1/sqrt(128)

    // ---- load Q fragments (fp32 -> scaled bf16 hi/lo), a-frag layout ----
    uint32_t qh[8][4], ql[8][4];
    {
        const float* qr0 = Qf + ((size_t)(b * SEQ + q0 + wm + r4)) * DMODEL + h * DHEAD;
        const float* qr1 = qr0 + (size_t)8 * DMODEL;
#pragma unroll
        for (int ks = 0; ks < 8; ks++) {
#pragma unroll
            for (int half = 0; half < 2; half++) {     // a0/a1 then a2/a3
                float2 v0 = *(const float2*)(qr0 + ks * 16 + half * 8 + c2);
                float2 v1 = *(const float2*)(qr1 + ks * 16 + half * 8 + c2);
                float f00 = v0.x * scale, f01 = v0.y * scale;
                float f10 = v1.x * scale, f11 = v1.y * scale;
                uint32_t h0 = pack_bf16x2(f00, f01);
                uint32_t h1 = pack_bf16x2(f10, f11);
                __nv_bfloat162 hb0 = *(__nv_bfloat162*)&h0;
                __nv_bfloat162 hb1 = *(__nv_bfloat162*)&h1;
                uint32_t l0 = pack_bf16x2(f00 - __bfloat162float(hb0.x),
                                          f01 - __bfloat162float(hb0.y));
                uint32_t l1 = pack_bf16x2(f10 - __bfloat162float(hb1.x),
                                          f11 - __bfloat162float(hb1.y));
                qh[ks][half * 2 + 0] = h0; qh[ks][half * 2 + 1] = h1;
                ql[ks][half * 2 + 0] = l0; ql[ks][half * 2 + 1] = l1;
            }
        }
    }

    float Oa[16][4];
#pragma unroll
    for (int t = 0; t < 16; t++)
#pragma unroll
        for (int c = 0; c < 4; c++) Oa[t][c] = 0.f;
    float m_i[2] = {-1e30f, -1e30f};
    float l_i[2] = {0.f, 0.f};

    const int ntile = (q0 + FBM) / FBN;    // 2*qb + 2

    const __nv_bfloat16* asrc[4] = {
        Kh + ((size_t)(b * SEQ)) * DMODEL + h * DHEAD,
        Kl + ((size_t)(b * SEQ)) * DMODEL + h * DHEAD,
        Vh + ((size_t)(b * SEQ)) * DMODEL + h * DHEAD,
        Vl + ((size_t)(b * SEQ)) * DMODEL + h * DHEAD };

    auto issue_loads = [&](int t) {
        const uint32_t so = sbase + (t & 1) * FSTAGE;
        const int k0 = t * FBN;
#pragma unroll
        for (int j = 0; j < 16; j++) {
            int idx = j * 256 + tid;            // 0..4095
            int arr  = idx >> 10;               // 0..3
            int g    = idx & 1023;
            int row  = g >> 4;                  // 0..63
            int gran = g & 15;                  // 16B granule: d = gran*8
            const __nv_bfloat16* src = asrc[arr] + (size_t)(k0 + row) * DMODEL + gran * 8;
            uint32_t dst = so + arr * FARR + (gran >> 2) * FCH + row * 80 + (gran & 3) * 16;
            CP_ASYNC16(dst, src);
        }
        CP_COMMIT();
    };

    issue_loads(0);

    for (int t = 0; t < ntile; t++) {
        if (t + 1 < ntile) {
            issue_loads(t + 1);
            CP_WAIT(1);
        } else {
            CP_WAIT(0);
        }
        __syncthreads();

        const int k0 = t * FBN;
        const bool skip = (k0 > q0 + wm + 15);

        if (!skip) {
            const uint32_t so = sbase + (t & 1) * FSTAGE;
            const uint32_t kh_s = so + 0 * FARR;
            const uint32_t kl_s = so + 1 * FARR;
            const uint32_t vh_s = so + 2 * FARR;
            const uint32_t vl_s = so + 3 * FARR;

            // ---- scores S[8 n8-tiles][4] ----
            float S[8][4];
#pragma unroll
            for (int j = 0; j < 8; j++)
#pragma unroll
                for (int c = 0; c < 4; c++) S[j][c] = 0.f;

#pragma unroll
            for (int ks = 0; ks < 8; ks++) {
                const uint32_t co = (ks >> 1) * FCH + (ks & 1) * 32 + lcolb;
                uint32_t khf[8][2], klf[8][2];
#pragma unroll
                for (int g = 0; g < 4; g++) {
                    uint32_t r0, r1, r2, r3;
                    ldsm_x4(r0, r1, r2, r3, kh_s + co + (g * 16 + lrow) * 80);
                    khf[g * 2 + 0][0] = r0; khf[g * 2 + 0][1] = r2;
                    khf[g * 2 + 1][0] = r1; khf[g * 2 + 1][1] = r3;
                    ldsm_x4(r0, r1, r2, r3, kl_s + co + (g * 16 + lrow) * 80);
                    klf[g * 2 + 0][0] = r0; klf[g * 2 + 0][1] = r2;
                    klf[g * 2 + 1][0] = r1; klf[g * 2 + 1][1] = r3;
                }
#pragma unroll
                for (int j = 0; j < 8; j++) {
                    mma_bf16(S[j], qh[ks], khf[j]);
                    mma_bf16(S[j], qh[ks], klf[j]);
                    mma_bf16(S[j], ql[ks], khf[j]);
                }
            }

            // ---- causal mask ----
            const int qg0 = q0 + wm + r4;
            const int qg1 = qg0 + 8;
            if (k0 + FBN - 1 > q0 + wm) {
#pragma unroll
                for (int j = 0; j < 8; j++) {
                    int kc = k0 + j * 8 + c2;
                    if (kc     > qg0) S[j][0] = -1e30f;
                    if (kc + 1 > qg0) S[j][1] = -1e30f;
                    if (kc     > qg1) S[j][2] = -1e30f;
                    if (kc + 1 > qg1) S[j][3] = -1e30f;
                }
            }

            // ---- online softmax ----
            float mx0 = -1e30f, mx1 = -1e30f;
#pragma unroll
            for (int j = 0; j < 8; j++) {
                mx0 = fmaxf(mx0, fmaxf(S[j][0], S[j][1]));
                mx1 = fmaxf(mx1, fmaxf(S[j][2], S[j][3]));
            }
            mx0 = fmaxf(mx0, __shfl_xor_sync(0xffffffffu, mx0, 1));
            mx0 = fmaxf(mx0, __shfl_xor_sync(0xffffffffu, mx0, 2));
            mx1 = fmaxf(mx1, __shfl_xor_sync(0xffffffffu, mx1, 1));
            mx1 = fmaxf(mx1, __shfl_xor_sync(0xffffffffu, mx1, 2));

            float mn0 = fmaxf(m_i[0], mx0);
            float mn1 = fmaxf(m_i[1], mx1);
            float a0 = __expf(m_i[0] - mn0);
            float a1 = __expf(m_i[1] - mn1);

            float s0 = 0.f, s1 = 0.f;
#pragma unroll
            for (int j = 0; j < 8; j++) {
                float e0 = (S[j][0] > -5e29f) ? __expf(S[j][0] - mn0) : 0.f;
                float e1 = (S[j][1] > -5e29f) ? __expf(S[j][1] - mn0) : 0.f;
                float e2 = (S[j][2] > -5e29f) ? __expf(S[j][2] - mn1) : 0.f;
                float e3 = (S[j][3] > -5e29f) ? __expf(S[j][3] - mn1) : 0.f;
                S[j][0] = e0; S[j][1] = e1; S[j][2] = e2; S[j][3] = e3;
                s0 += e0 + e1; s1 += e2 + e3;
            }
            s0 += __shfl_xor_sync(0xffffffffu, s0, 1);
            s0 += __shfl_xor_sync(0xffffffffu, s0, 2);
            s1 += __shfl_xor_sync(0xffffffffu, s1, 1);
            s1 += __shfl_xor_sync(0xffffffffu, s1, 2);

            l_i[0] = l_i[0] * a0 + s0;
            l_i[1] = l_i[1] * a1 + s1;
            m_i[0] = mn0; m_i[1] = mn1;
#pragma unroll
            for (int tt = 0; tt < 16; tt++) {
                Oa[tt][0] *= a0; Oa[tt][1] *= a0;
                Oa[tt][2] *= a1; Oa[tt][3] *= a1;
            }

            // ---- pack P into bf16 hi/lo a-fragments (4 k-steps) ----
            uint32_t ph[4][4], pl[4][4];
#pragma unroll
            for (int ks = 0; ks < 4; ks++) {
#pragma unroll
                for (int half = 0; half < 2; half++) {   // tile 2ks, 2ks+1
                    float v0 = S[2 * ks + half][0], v1 = S[2 * ks + half][1];
                    float v2 = S[2 * ks + half][2], v3 = S[2 * ks + half][3];
                    uint32_t h0 = pack_bf16x2(v0, v1);
                    uint32_t h1 = pack_bf16x2(v2, v3);
                    __nv_bfloat162 hb0 = *(__nv_bfloat162*)&h0;
                    __nv_bfloat162 hb1 = *(__nv_bfloat162*)&h1;
                    uint32_t l0 = pack_bf16x2(v0 - __bfloat162float(hb0.x),
                                              v1 - __bfloat162float(hb0.y));
                    uint32_t l1 = pack_bf16x2(v2 - __bfloat162float(hb1.x),
                                              v3 - __bfloat162float(hb1.y));
                    ph[ks][half * 2 + 0] = h0; ph[ks][half * 2 + 1] = h1;
                    pl[ks][half * 2 + 0] = l0; pl[ks][half * 2 + 1] = l1;
                }
            }

            // ---- P @ V ----
#pragma unroll
            for (int ks = 0; ks < 4; ks++) {
#pragma unroll
                for (int tp = 0; tp < 8; tp++) {   // d-tile pair (2tp, 2tp+1)
                    int dbase = tp * 16;                      // d elems
                    int g2 = lid >> 3;                        // matrix idx 0..3
                    int rr = lid & 7;
                    int seqrow = ks * 16 + (g2 & 1) * 8 + rr;
                    int de = dbase + (g2 >> 1) * 8;
                    uint32_t addr_off = (de >> 5) * FCH + seqrow * 80 + ((de & 31) >> 3) * 16;
                    uint32_t b0, b1, b2, b3;
                    ldsm_x4_t(b0, b1, b2, b3, vh_s + addr_off);
                    uint32_t vhf0[2] = {b0, b1}, vhf1[2] = {b2, b3};
                    ldsm_x4_t(b0, b1, b2, b3, vl_s + addr_off);
                    uint32_t vlf0[2] = {b0, b1}, vlf1[2] = {b2, b3};
                    mma_bf16(Oa[2 * tp],     ph[ks], vhf0);
                    mma_bf16(Oa[2 * tp],     pl[ks], vhf0);
                    mma_bf16(Oa[2 * tp],     ph[ks], vlf0);
                    mma_bf16(Oa[2 * tp + 1], ph[ks], vhf1);
                    mma_bf16(Oa[2 * tp + 1], pl[ks], vhf1);
                    mma_bf16(Oa[2 * tp + 1], ph[ks], vlf1);
                }
            }
        }
        __syncthreads();
    }

    // ---- write out ----
    float inv0 = 1.0f / l_i[0];
    float inv1 = 1.0f / l_i[1];
    float* or0 = O + ((size_t)(b * SEQ + q0 + wm + r4)) * DMODEL + h * DHEAD;
    float* or1 = or0 + (size_t)8 * DMODEL;
#pragma unroll
    for (int tt = 0; tt < 16; tt++) {
        *(float2*)(or0 + tt * 8 + c2) = make_float2(Oa[tt][0] * inv0, Oa[tt][1] * inv0);
        *(float2*)(or1 + tt * 8 + c2) = make_float2(Oa[tt][2] * inv1, Oa[tt][3] * inv1);
    }
}

// ---------------- launch --------------------------------------------------------
extern "C" void kernel_launch(void* const* d_in, const int* in_sizes, int n_in,
                              void* d_out, int out_size) {
    const float* x  = (const float*)d_in[0];
    const float* wq = (const float*)d_in[1];
    const float* wk = (const float*)d_in[2];
    const float* wv = (const float*)d_in[3];
    const float* wo = (const float*)d_in[4];
    float* out = (float*)d_out;

    float *q, *k, *v, *o;
    cudaGetSymbolAddress((void**)&q, g_q);
    cudaGetSymbolAddress((void**)&k, g_k);
    cudaGetSymbolAddress((void**)&v, g_v);
    cudaGetSymbolAddress((void**)&o, g_o);
    __nv_bfloat16 *xh, *xl, *oh, *ol, *kh, *kl, *vh, *vl;
    __nv_bfloat16 *wqh, *wql, *wkh, *wkl, *wvh, *wvl, *woh, *wol;
    cudaGetSymbolAddress((void**)&xh, g_xh);   cudaGetSymbolAddress((void**)&xl, g_xl);
    cudaGetSymbolAddress((void**)&oh, g_oh);   cudaGetSymbolAddress((void**)&ol, g_ol);
    cudaGetSymbolAddress((void**)&kh, g_kh);   cudaGetSymbolAddress((void**)&kl, g_kl);
    cudaGetSymbolAddress((void**)&vh, g_vh);   cudaGetSymbolAddress((void**)&vl, g_vl);
    cudaGetSymbolAddress((void**)&wqh, g_wqh); cudaGetSymbolAddress((void**)&wql, g_wql);
    cudaGetSymbolAddress((void**)&wkh, g_wkh); cudaGetSymbolAddress((void**)&wkl, g_wkl);
    cudaGetSymbolAddress((void**)&wvh, g_wvh); cudaGetSymbolAddress((void**)&wvl, g_wvl);
    cudaGetSymbolAddress((void**)&woh, g_woh); cudaGetSymbolAddress((void**)&wol, g_wol);

    const int NX4 = MTOT * DMODEL / 4;
    const int NW4 = DMODEL * DMODEL / 4;

    split_bf16<<<NX4 / 256, 256>>>(x,  xh,  xl,  NX4);
    split_bf16<<<NW4 / 256, 256>>>(wq, wqh, wql, NW4);
    split_bf16<<<NW4 / 256, 256>>>(wk, wkh, wkl, NW4);
    split_bf16<<<NW4 / 256, 256>>>(wv, wvh, wvl, NW4);
    split_bf16<<<NW4 / 256, 256>>>(wo, woh, wol, NW4);

    cudaFuncSetAttribute(gemm_hmma, cudaFuncAttributeMaxDynamicSharedMemorySize, GSMEM);
    dim3 gg(DMODEL / GBN, MTOT / GBM);
    gemm_hmma<<<gg, 256, GSMEM>>>(xh, xl, wqh, wql, q, MTOT, DMODEL, DMODEL);
    gemm_hmma<<<gg, 256, GSMEM>>>(xh, xl, wkh, wkl, k, MTOT, DMODEL, DMODEL);
    gemm_hmma<<<gg, 256, GSMEM>>>(xh, xl, wvh, wvl, v, MTOT, DMODEL, DMODEL);

    int rope_total = B_SZ * SEQ * NHEAD * (DHEAD / 2);
    rope_kernel<<<(rope_total + 255) / 256, 256>>>(q);
    rope_kernel<<<(rope_total + 255) / 256, 256>>>(k);

    // K, V -> bf16 hi/lo for tensor-core attention
    split_bf16<<<NX4 / 256, 256>>>(k, kh, kl, NX4);
    split_bf16<<<NX4 / 256, 256>>>(v, vh, vl, NX4);

    cudaFuncSetAttribute(flash_hmma, cudaFuncAttributeMaxDynamicSharedMemorySize, FSMEM);
    flash_hmma<<<dim3(SEQ / FBM, NHEAD, B_SZ), 256, FSMEM>>>(q, kh, kl, vh, vl, o);

    split_bf16<<<NX4 / 256, 256>>>(o, oh, ol, NX4);
    gemm_hmma<<<gg, 256, GSMEM>>>(oh, ol, woh, wol, out, MTOT, DMODEL, DMODEL);
}